// round 1
// baseline (speedup 1.0000x reference)
#include <cuda_runtime.h>

#define HW    2048
#define MASK  2047
#define BATCH 4
#define TX    32
#define TY    16
#define NTHR  (TX*TY)

// Kobayashi dendrite single timestep, fused, periodic boundaries.
// Stage 1: per grid point (tile + halo1) compute
//   prod1 = eps*eps_deriv*phidx, prod2 = -eps*eps_deriv*phidy, eps^2
//   using the trig-free identity cos/sin(6*theta) = Re/Im(z^6)/r^6, z = phidx + i*phidy.
// Stage 2: assemble dphi_dt and both outputs.
__global__ __launch_bounds__(NTHR, 4)
void dendrite_kernel(const float* __restrict__ phi,
                     const float* __restrict__ tempr,
                     float* __restrict__ out)
{
    __shared__ float sphi[TY + 4][TX + 4];   // phi, halo 2  : [20][36]
    __shared__ float stmp[TY + 2][TX + 2];   // tempr, halo 1: [18][34]
    __shared__ float sp1 [TY + 2][TX + 2];   // prod_mat1
    __shared__ float sp2 [TY + 2][TX + 2];   // prod_mat2
    __shared__ float se2 [TY + 2][TX + 2];   // epsilon^2

    const int tx  = threadIdx.x;
    const int ty  = threadIdx.y;
    const int tid = ty * TX + tx;
    const int x0  = blockIdx.x * TX;
    const int y0  = blockIdx.y * TY;
    const int b   = blockIdx.z;

    const float* __restrict__ pb = phi   + (size_t)b * HW * HW;
    const float* __restrict__ tb = tempr + (size_t)b * HW * HW;

    // ---- load phi tile (halo 2): (TY+4)*(TX+4) = 720 elements ----
    #pragma unroll
    for (int i = tid; i < (TY + 4) * (TX + 4); i += NTHR) {
        int j  = i / (TX + 4);
        int k  = i - j * (TX + 4);
        int gy = (y0 - 2 + j) & MASK;
        int gx = (x0 - 2 + k) & MASK;
        sphi[j][k] = pb[gy * HW + gx];
    }
    // ---- load tempr tile (halo 1): (TY+2)*(TX+2) = 612 elements ----
    #pragma unroll
    for (int i = tid; i < (TY + 2) * (TX + 2); i += NTHR) {
        int j  = i / (TX + 2);
        int k  = i - j * (TX + 2);
        int gy = (y0 - 1 + j) & MASK;
        int gx = (x0 - 1 + k) & MASK;
        stmp[j][k] = tb[gy * HW + gx];
    }
    __syncthreads();

    const float INV2D  = 1.0f / 0.06f;          // 1/(2*dx)
    const float C0     = 0.36235775447f;        // cos(6*theta0) = cos(1.2)
    const float S0     = 0.93203908597f;        // sin(6*theta0) = sin(1.2)
    const float EB     = 0.01f;                 // epsilonb
    const float EBD    = 0.01f * 0.02f;         // epsilonb*delta
    const float M6EBD  = -6.0f * 0.01f * 0.02f; // -aniso*epsilonb*delta

    // ---- stage 1: prod1/prod2/eps^2 over (TY+2)x(TX+2) region ----
    #pragma unroll
    for (int i = tid; i < (TY + 2) * (TX + 2); i += NTHR) {
        int yy = i / (TX + 2);
        int xx = i - yy * (TX + 2);
        // center of this stage-1 point in sphi coords: [yy+1][xx+1]
        float pxg = (sphi[yy + 1][xx + 2] - sphi[yy + 1][xx    ]) * INV2D;
        float pyg = (sphi[yy + 2][xx + 1] - sphi[yy    ][xx + 1]) * INV2D;

        float r2 = pxg * pxg + pyg * pyg;
        // z^2
        float a2 = pxg * pxg - pyg * pyg;
        float b2 = 2.0f * pxg * pyg;
        // z^3 = z^2 * z
        float a3 = a2 * pxg - b2 * pyg;
        float b3 = a2 * pyg + b2 * pxg;
        // z^6 = (z^3)^2
        float Az = a3 * a3 - b3 * b3;
        float Bz = 2.0f * a3 * b3;
        float r6 = r2 * r2 * r2;

        float c6, s6;
        if (r6 > 0.0f) {
            float ir6 = 1.0f / r6;
            c6 = Az * ir6;          // cos(6*theta)
            s6 = Bz * ir6;          // sin(6*theta)
        } else {                     // atan2(0,0) = 0 -> theta = 0
            c6 = 1.0f;
            s6 = 0.0f;
        }
        float u   = c6 * C0 + s6 * S0;     // cos(6*(theta - theta0))
        float v   = s6 * C0 - c6 * S0;     // sin(6*(theta - theta0))
        float eps = EB + EBD * u;          // epsilon
        float pc  = eps * (M6EBD * v);     // epsilon * epsilon_deriv

        sp1[yy][xx] =  pc * pxg;
        sp2[yy][xx] = -pc * pyg;
        se2[yy][xx] = eps * eps;
    }
    __syncthreads();

    // ---- stage 2: one output point per thread ----
    const float INVD2 = 1.0f / (0.03f * 0.03f);  // 1/dx^2 = 1/dy^2
    const float DTTAU = 0.33333334f;             // DT/TAU
    const float APIX  = 0.28647889757f;          // ALPHA/PI
    const float GAM   = 10.0f;
    const float KAP   = 1.8f;
    const float DTC   = 1e-4f;

    float c = sphi[ty + 2][tx + 2];
    float lapp = (sphi[ty + 2][tx + 3] + sphi[ty + 2][tx + 1] - 2.0f * c) * INVD2
               + (sphi[ty + 3][tx + 2] + sphi[ty + 1][tx + 2] - 2.0f * c) * INVD2;

    float t = stmp[ty + 1][tx + 1];
    float lapt = (stmp[ty + 1][tx + 2] + stmp[ty + 1][tx    ] - 2.0f * t) * INVD2
               + (stmp[ty + 2][tx + 1] + stmp[ty    ][tx + 1] - 2.0f * t) * INVD2;

    float term1 = (sp1[ty + 2][tx + 1] - sp1[ty    ][tx + 1]) * INV2D;
    float term2 = (sp2[ty + 1][tx + 2] - sp2[ty + 1][tx    ]) * INV2D;

    float m  = APIX * atanf(GAM * (1.0f - t));
    float e2 = se2[ty + 1][tx + 1];

    float dphi = DTTAU * (term1 + term2 + e2 * lapp
                          + c * (1.0f - c) * (c - 0.5f + m));

    float outp = c + dphi;
    float outt = t + DTC * lapt + KAP * dphi;

    size_t idx = (size_t)b * HW * HW + (size_t)(y0 + ty) * HW + (x0 + tx);
    out[idx] = outp;
    out[(size_t)BATCH * HW * HW + idx] = outt;
}

extern "C" void kernel_launch(void* const* d_in, const int* in_sizes, int n_in,
                              void* d_out, int out_size)
{
    const float* phi   = (const float*)d_in[0];
    const float* tempr = (const float*)d_in[1];
    float* out = (float*)d_out;

    dim3 block(TX, TY);
    dim3 grid(HW / TX, HW / TY, BATCH);
    dendrite_kernel<<<grid, block>>>(phi, tempr, out);
}

// round 2
// speedup vs baseline: 2.0519x; 2.0519x over previous
#include <cuda_runtime.h>

#define HW    2048
#define MASK  2047
#define BATCH 4
#define SY    256          // rows per warp strip
#define WPB   4            // warps per block
#define NSTRIP_X 76        // ceil(2048/28)=74, padded to 76 (4 warps/block); extra strips write wrapped duplicates (identical values)

// constants (folded)
#define C0f     0.3623577545f      // cos(1.2)
#define S0f     0.9320390860f      // sin(1.2)
#define EBf     0.01f
#define EBDf    0.0002f            // epsilonb*delta
#define M6EBDf  (-0.0012f)         // -aniso*epsilonb*delta
#define KAf     92.59259259f       // (DT/TAU)/(2dx)^2
#define KBf     370.3703704f       // (DT/TAU)/dx^2
#define KTf     0.1111111111f      // DT/dx^2
#define KAPf    1.8f
#define DTTAUf  0.3333333333f
#define APIXf   0.2864788976f      // alpha/pi
#define PIO2f   1.5707963268f

__device__ __forceinline__ void stage1(float L, float R, float dn, float up,
                                       float& P1, float& P2, float& E2)
{
    // unscaled central differences; theta is invariant under common positive scaling
    float dx  = R - L;
    float dy  = up - dn;
    float dx2 = dx * dx;
    float r2  = fmaf(dy, dy, dx2);
    float a2  = fmaf(-dy, dy, dx2);          // dx^2 - dy^2
    float b2  = 2.0f * dx * dy;
    float a3  = fmaf(a2, dx, -(b2 * dy));
    float b3  = fmaf(a2, dy,  (b2 * dx));
    float Az  = fmaf(a3, a3, -(b3 * b3));    // Re(z^6)
    float Bz  = 2.0f * a3 * b3;              // Im(z^6)
    float r6  = r2 * r2 * r2;
    float ir6 = __fdividef(1.0f, fmaxf(r6, 1e-30f));
    float u   = fmaf(Az, C0f,  (Bz * S0f)) * ir6;   // cos(6(theta-theta0))
    float v   = fmaf(Bz, C0f, -(Az * S0f)) * ir6;   // sin(6(theta-theta0))
    float eps = fmaf(EBDf, u, EBf);
    float pc  = eps * (M6EBDf * v);          // eps * eps_deriv
    P1 =  pc * dx;                            // unscaled prod1 (INV2D folded into KA)
    P2 = -pc * dy;                            // unscaled prod2
    E2 = eps * eps;
}

__device__ __forceinline__ float atan_pos(float g)
{
    // atan for g in (0, 10]; minimax odd poly on [0,1] + reciprocal identity
    float inv = __fdividef(1.0f, g);
    bool  big = g > 1.0f;
    float w   = big ? inv : g;
    float w2  = w * w;
    float p   = fmaf(w2, -0.01172120f, 0.05265332f);
    p = fmaf(w2, p, -0.11643287f);
    p = fmaf(w2, p,  0.19354346f);
    p = fmaf(w2, p, -0.33262347f);
    p = fmaf(w2, p,  0.99997726f);
    p = p * w;
    return big ? (PIO2f - p) : p;
}

__global__ __launch_bounds__(WPB * 32, 8)
void dendrite_sweep(const float* __restrict__ phi,
                    const float* __restrict__ tempr,
                    float* __restrict__ out)
{
    const unsigned FULL = 0xffffffffu;
    const int lane  = threadIdx.x & 31;
    const int wid   = threadIdx.x >> 5;
    const int strip = blockIdx.x * WPB + wid;       // 0..75
    const int b     = blockIdx.z;
    const int y0    = blockIdx.y * SY;

    const int xc = (strip * 28 + lane - 2) & MASK;  // column owned by this lane (wrapped)
    const int lm = lane - 1;
    const int lp = lane + 1;

    const float* __restrict__ pb = phi   + (size_t)b * HW * HW + xc;
    const float* __restrict__ tb = tempr + (size_t)b * HW * HW + xc;
    float* __restrict__ po = out + (size_t)b * HW * HW + xc;
    float* __restrict__ to = out + (size_t)BATCH * HW * HW + (size_t)b * HW * HW + xc;

    // ---- prologue: load phi rows y0-2..y0+3, tempr rows y0-1..y0+2 ----
    float pm2 = pb[((y0 - 2) & MASK) * HW];
    float pm1 = pb[((y0 - 1) & MASK) * HW];
    float p0  = pb[ y0                * HW];
    float pp1 = pb[((y0 + 1) & MASK) * HW];
    float pp2 = pb[((y0 + 2) & MASK) * HW];
    float pp3 = pb[((y0 + 3) & MASK) * HW];

    float tm1 = tb[((y0 - 1) & MASK) * HW];
    float t0  = tb[ y0                * HW];
    float tp1 = tb[((y0 + 1) & MASK) * HW];
    float tp2 = tb[((y0 + 2) & MASK) * HW];

    // stage1 at row y0-1 (only P1 needed) and y0
    float P1m, P2m, E2m, P1c, P2c, E2c;
    {
        float L = __shfl_sync(FULL, pm1, lm);
        float R = __shfl_sync(FULL, pm1, lp);
        stage1(L, R, pm2, p0, P1m, P2m, E2m);
    }
    {
        float L = __shfl_sync(FULL, p0, lm);
        float R = __shfl_sync(FULL, p0, lp);
        stage1(L, R, pm1, pp1, P1c, P2c, E2c);
    }

    const bool wr = (lane >= 2) && (lane < 30);

    #pragma unroll 4
    for (int i = 0; i < SY; ++i) {
        const int y = y0 + i;

        // prefetch (distance-2): phi(y+4), tempr(y+3)
        float pp4 = pb[((y + 4) & MASK) * HW];
        float tp3 = tb[((y + 3) & MASK) * HW];

        // stage1 at row y+1
        float P1n, P2n, E2n;
        {
            float L = __shfl_sync(FULL, pp1, lm);
            float R = __shfl_sync(FULL, pp1, lp);
            stage1(L, R, p0, pp2, P1n, P2n, E2n);
        }

        // stage2 at row y  (valid on lanes 2..29)
        float L0  = __shfl_sync(FULL, p0,  lm);
        float R0  = __shfl_sync(FULL, p0,  lp);
        float Lt  = __shfl_sync(FULL, t0,  lm);
        float Rt  = __shfl_sync(FULL, t0,  lp);
        float P2L = __shfl_sync(FULL, P2c, lm);
        float P2R = __shfl_sync(FULL, P2c, lp);

        float lapp = (pp1 + pm1) + (L0 + R0);
        lapp = fmaf(p0, -4.0f, lapp);                 // unscaled 5-pt laplacian of phi
        float lapt = (tp1 + tm1) + (Lt + Rt);
        lapt = fmaf(t0, -4.0f, lapt);                 // unscaled laplacian of tempr

        float term = (P1n - P1m) + (P2R - P2L);       // unscaled term1+term2

        float g    = fmaf(t0, -10.0f, 10.0f);         // GAMMA*(TEQ - tempr)
        float at   = atan_pos(g);
        float c05  = p0 - 0.5f;
        float marg = fmaf(APIXf, at, c05);            // phi - 0.5 + m
        float q    = fmaf(-p0, p0, p0);               // phi*(1-phi)
        float poly = q * marg;

        float d1   = term * KAf;
        d1 = fmaf(E2c * lapp, KBf, d1);
        float dphi = fmaf(poly, DTTAUf, d1);

        if (wr) {
            po[y * HW] = p0 + dphi;
            to[y * HW] = fmaf(KAPf, dphi, fmaf(KTf, lapt, t0));
        }

        // ring shifts
        pm1 = p0;  p0 = pp1;  pp1 = pp2;  pp2 = pp3;  pp3 = pp4;
        tm1 = t0;  t0 = tp1;  tp1 = tp2;  tp2 = tp3;
        P1m = P1c; P1c = P1n; P2c = P2n; E2c = E2n;
    }
}

extern "C" void kernel_launch(void* const* d_in, const int* in_sizes, int n_in,
                              void* d_out, int out_size)
{
    const float* phi   = (const float*)d_in[0];
    const float* tempr = (const float*)d_in[1];
    float* out = (float*)d_out;

    dim3 block(WPB * 32);
    dim3 grid(NSTRIP_X / WPB, HW / SY, BATCH);   // (19, 8, 4)
    dendrite_sweep<<<grid, block>>>(phi, tempr, out);
}

// round 3
// speedup vs baseline: 2.2766x; 1.1095x over previous
#include <cuda_runtime.h>

#define HW    2048
#define HW2   1024
#define MASK  2047
#define BATCH 4
#define SY    64
#define WPB   4
#define NSTRIP 36          // 36*60 = 2160 >= 2048; overlap strips write identical wrapped values

// folded constants
#define C0f     0.3623577545f      // cos(1.2)
#define S0f     0.9320390860f      // sin(1.2)
#define EBf     0.01f
#define EBDf    0.0002f            // epsilonb*delta
#define M6EBDf  (-0.0012f)         // -aniso*epsilonb*delta
#define KAf     92.59259259f       // (DT/TAU)/(2dx)^2
#define KBf     370.3703704f       // (DT/TAU)/dx^2
#define KTf     0.1111111111f      // DT/dx^2
#define KAPf    1.8f
#define DTTAUf  0.3333333333f
#define APIXf   0.2864788976f      // alpha/pi
#define PIO2f   1.5707963268f

__device__ __forceinline__ void stage1(float L, float R, float dn, float up,
                                       float& P1, float& P2, float& E2)
{
    // unscaled central differences; theta invariant under common positive scaling
    float dx  = R - L;
    float dy  = up - dn;
    float dx2 = dx * dx;
    float r2  = fmaf(dy, dy, dx2);
    float a2  = fmaf(-dy, dy, dx2);          // dx^2 - dy^2
    float b2  = 2.0f * dx * dy;
    float a3  = fmaf(a2, dx, -(b2 * dy));
    float b3  = fmaf(a2, dy,  (b2 * dx));
    float Az  = fmaf(a3, a3, -(b3 * b3));    // Re(z^6)
    float Bz  = 2.0f * a3 * b3;              // Im(z^6)
    float r6  = r2 * r2 * r2;
    float ir6 = __fdividef(1.0f, fmaxf(r6, 1e-30f));
    float u   = fmaf(Az, C0f,  (Bz * S0f)) * ir6;   // cos(6(theta-theta0))
    float v   = fmaf(Bz, C0f, -(Az * S0f)) * ir6;   // sin(6(theta-theta0))
    float eps = fmaf(EBDf, u, EBf);
    float pc  = eps * (M6EBDf * v);          // eps * eps_deriv
    P1 =  pc * dx;
    P2 = -pc * dy;
    E2 = eps * eps;
}

__device__ __forceinline__ float atan_pos(float g)
{
    // atan for g in (0, 10]; minimax odd poly on [0,1] + reciprocal identity
    float inv = __fdividef(1.0f, g);
    bool  big = g > 1.0f;
    float w   = big ? inv : g;
    float w2  = w * w;
    float p   = fmaf(w2, -0.01172120f, 0.05265332f);
    p = fmaf(w2, p, -0.11643287f);
    p = fmaf(w2, p,  0.19354346f);
    p = fmaf(w2, p, -0.33262347f);
    p = fmaf(w2, p,  0.99997726f);
    p = p * w;
    return big ? (PIO2f - p) : p;
}

__global__ __launch_bounds__(WPB * 32, 6)
void dendrite_sweep2(const float* __restrict__ phi,
                     const float* __restrict__ tempr,
                     float* __restrict__ out)
{
    const unsigned FULL = 0xffffffffu;
    const int lane  = threadIdx.x & 31;
    const int wid   = threadIdx.x >> 5;
    const int strip = blockIdx.x * WPB + wid;       // 0..35
    const int b     = blockIdx.z;
    const int y0    = blockIdx.y * SY;
    const int lm    = lane - 1;
    const int lp    = lane + 1;

    const int xc = (strip * 60 - 2 + 2 * lane) & MASK;   // even column pair base
    const size_t base = (size_t)b * HW * HW;
    const float2* __restrict__ pb = (const float2*)(phi   + base) + (xc >> 1);
    const float2* __restrict__ tb = (const float2*)(tempr + base) + (xc >> 1);
    float2* __restrict__ po = (float2*)(out + base) + (xc >> 1);
    float2* __restrict__ to = (float2*)(out + (size_t)BATCH * HW * HW + base) + (xc >> 1);

#define PROW(r) pb[((r) & MASK) * HW2]
#define TROW(r) tb[((r) & MASK) * HW2]

    // prologue loads
    float2 pm2 = PROW(y0 - 2), pm1 = PROW(y0 - 1), p0 = PROW(y0);
    float2 pp1 = PROW(y0 + 1), pp2 = PROW(y0 + 2), pp3 = PROW(y0 + 3);
    float2 tm1 = TROW(y0 - 1), t0 = TROW(y0);
    float2 tp1 = TROW(y0 + 1), tp2 = TROW(y0 + 2);

    // stage1 at row y0-1 (P1 only) and y0
    float2 P1m, P1c, P2c, E2c;
    {
        float Lc = __shfl_sync(FULL, pm1.y, lm);
        float Rc = __shfl_sync(FULL, pm1.x, lp);
        float d0, d1;
        stage1(Lc,    pm1.y, pm2.x, p0.x, P1m.x, d0, d1);
        stage1(pm1.x, Rc,    pm2.y, p0.y, P1m.y, d0, d1);
    }
    {
        float Lc = __shfl_sync(FULL, p0.y, lm);
        float Rc = __shfl_sync(FULL, p0.x, lp);
        stage1(Lc,   p0.y, pm1.x, pp1.x, P1c.x, P2c.x, E2c.x);
        stage1(p0.x, Rc,   pm1.y, pp1.y, P1c.y, P2c.y, E2c.y);
    }

    const bool wr = (lane >= 1) && (lane <= 30);

    #pragma unroll 4
    for (int i = 0; i < SY; ++i) {
        const int y = y0 + i;

        // prefetch distance-2
        float2 pp4 = PROW(y + 4);
        float2 tp3 = TROW(y + 3);

        // stage1 at row y+1
        float2 P1n, P2n, E2n;
        {
            float Lc = __shfl_sync(FULL, pp1.y, lm);
            float Rc = __shfl_sync(FULL, pp1.x, lp);
            stage1(Lc,    pp1.y, p0.x, pp2.x, P1n.x, P2n.x, E2n.x);
            stage1(pp1.x, Rc,    p0.y, pp2.y, P1n.y, P2n.y, E2n.y);
        }

        // x-neighbor shuffles for stage2 at row y
        float Lp  = __shfl_sync(FULL, p0.y,  lm);
        float Rp  = __shfl_sync(FULL, p0.x,  lp);
        float Lt  = __shfl_sync(FULL, t0.y,  lm);
        float Rt  = __shfl_sync(FULL, t0.x,  lp);
        float LP2 = __shfl_sync(FULL, P2c.y, lm);
        float RP2 = __shfl_sync(FULL, P2c.x, lp);

        float2 outp, outt;
        {   // element .x (column xc)
            float lapp = (pp1.x + pm1.x) + (Lp + p0.y);
            lapp = fmaf(p0.x, -4.0f, lapp);
            float lapt = (tp1.x + tm1.x) + (Lt + t0.y);
            lapt = fmaf(t0.x, -4.0f, lapt);
            float term = (P1n.x - P1m.x) + (P2c.y - LP2);
            float at   = atan_pos(fmaf(t0.x, -10.0f, 10.0f));
            float marg = fmaf(APIXf, at, p0.x - 0.5f);
            float q    = fmaf(-p0.x, p0.x, p0.x);
            float d1   = term * KAf;
            d1 = fmaf(E2c.x * lapp, KBf, d1);
            float dphi = fmaf(q * marg, DTTAUf, d1);
            outp.x = p0.x + dphi;
            outt.x = fmaf(KAPf, dphi, fmaf(KTf, lapt, t0.x));
        }
        {   // element .y (column xc+1)
            float lapp = (pp1.y + pm1.y) + (p0.x + Rp);
            lapp = fmaf(p0.y, -4.0f, lapp);
            float lapt = (tp1.y + tm1.y) + (t0.x + Rt);
            lapt = fmaf(t0.y, -4.0f, lapt);
            float term = (P1n.y - P1m.y) + (RP2 - P2c.x);
            float at   = atan_pos(fmaf(t0.y, -10.0f, 10.0f));
            float marg = fmaf(APIXf, at, p0.y - 0.5f);
            float q    = fmaf(-p0.y, p0.y, p0.y);
            float d1   = term * KAf;
            d1 = fmaf(E2c.y * lapp, KBf, d1);
            float dphi = fmaf(q * marg, DTTAUf, d1);
            outp.y = p0.y + dphi;
            outt.y = fmaf(KAPf, dphi, fmaf(KTf, lapt, t0.y));
        }

        if (wr) {
            po[y * HW2] = outp;
            to[y * HW2] = outt;
        }

        // ring shifts (renamed away by unrolling)
        pm1 = p0;  p0 = pp1;  pp1 = pp2;  pp2 = pp3;  pp3 = pp4;
        tm1 = t0;  t0 = tp1;  tp1 = tp2;  tp2 = tp3;
        P1m = P1c; P1c = P1n; P2c = P2n; E2c = E2n;
    }
#undef PROW
#undef TROW
}

extern "C" void kernel_launch(void* const* d_in, const int* in_sizes, int n_in,
                              void* d_out, int out_size)
{
    const float* phi   = (const float*)d_in[0];
    const float* tempr = (const float*)d_in[1];
    float* out = (float*)d_out;

    dim3 block(WPB * 32);
    dim3 grid(NSTRIP / WPB, HW / SY, BATCH);   // (9, 32, 4)
    dendrite_sweep2<<<grid, block>>>(phi, tempr, out);
}